// round 3
// baseline (speedup 1.0000x reference)
#include <cuda_runtime.h>
#include <cuda_bf16.h>
#include <cuda_fp16.h>
#include <cstdint>

#define DINLINE __device__ __forceinline__

static constexpr int B_ROWS = 4096;
static constexpr int D_DIM  = 256;
static constexpr int N_TOT  = 8192;
static constexpr int TILE   = 128;
static constexpr int COL_SPLITS   = 2;
static constexpr int COLS_PER_CTA = N_TOT / COL_SPLITS;   // 4096
static constexpr int NTILES       = COLS_PER_CTA / TILE;  // 32

static constexpr float EXP_K = 2.8853900817779268f;  // 2 / ln(2): exp(2s) = 2^(s*K)

// ---- device scratch (no allocations allowed) ----
__device__ __align__(16) __half g_Z[N_TOT * D_DIM];          // normalized, fp16
__device__ float g_denom[COL_SPLITS * N_TOT];                 // partial raw denominators (incl. diag)

// ============ helpers ============
DINLINE uint32_t smem_u32(const void* p) {
    uint32_t a;
    asm("{ .reg .u64 t; cvta.to.shared.u64 t, %1; cvt.u32.u64 %0, t; }" : "=r"(a) : "l"(p));
    return a;
}

DINLINE void ldsm_x4(uint32_t addr, uint32_t r[4]) {
    asm volatile("ldmatrix.sync.aligned.m8n8.x4.shared.b16 {%0,%1,%2,%3}, [%4];"
                 : "=r"(r[0]), "=r"(r[1]), "=r"(r[2]), "=r"(r[3]) : "r"(addr));
}

// f16 x f16 -> f16 accumulate (double-rate mma.sync path)
DINLINE void mma16816_f16(uint32_t c[2], const uint32_t a[4], uint32_t b0, uint32_t b1) {
    asm volatile(
        "mma.sync.aligned.m16n8k16.row.col.f16.f16.f16.f16 "
        "{%0,%1}, {%2,%3,%4,%5}, {%6,%7}, {%0,%1};"
        : "+r"(c[0]), "+r"(c[1])
        : "r"(a[0]), "r"(a[1]), "r"(a[2]), "r"(a[3]), "r"(b0), "r"(b1));
}

DINLINE float ex2f(float x) {
    float e;
    asm("ex2.approx.f32 %0, %1;" : "=f"(e) : "f"(x));
    return e;
}

// ============ SMEM layout (dynamic) ============
// Tiles row-major [128 rows][256 fp16 cols] + 16B row pad: stride 528 B.
// ldmatrix row starts hit banks 4r mod 32 -> conflict-free.
static constexpr int ROW_BYTES  = 528;
static constexpr int TILE_BYTES = 128 * ROW_BYTES;  // 67584
static constexpr int SMEM_DSUM  = 0;                // 128 floats
static constexpr int SMEM_A     = 1024;
static constexpr int SMEM_B0    = SMEM_A + TILE_BYTES;
static constexpr int SMEM_B1    = SMEM_B0 + TILE_BYTES;
static constexpr int SMEM_TOTAL = SMEM_B1 + TILE_BYTES;  // 203776

DINLINE void load_tile(uint32_t smem_dst, const __half* gsrc, int tid) {
#pragma unroll
    for (int i = 0; i < 16; ++i) {
        int u = tid + i * 256;                 // 0..4095 16B units
        int r = u >> 5, c = u & 31;
        uint32_t saddr = smem_dst + (uint32_t)r * ROW_BYTES + (uint32_t)c * 16;
        const char* g = (const char*)gsrc + (size_t)u * 16;
        asm volatile("cp.async.cg.shared.global [%0], [%1], 16;" :: "r"(saddr), "l"(g));
    }
}

// ============ kernel 1: row L2-normalize, fp32 -> fp16 Z; also zero d_out ============
__global__ void __launch_bounds__(64) k_normalize(const float* __restrict__ q,
                                                  const float* __restrict__ p,
                                                  float* __restrict__ out) {
    int row = blockIdx.x;
    if (row == 0 && threadIdx.x == 0) out[0] = 0.0f;
    const float* src = (row < B_ROWS) ? q + (size_t)row * D_DIM
                                      : p + (size_t)(row - B_ROWS) * D_DIM;
    int t = threadIdx.x;
    float4 v = ((const float4*)src)[t];
    float ss = v.x * v.x + v.y * v.y + v.z * v.z + v.w * v.w;
#pragma unroll
    for (int o = 16; o; o >>= 1) ss += __shfl_xor_sync(0xffffffffu, ss, o);
    __shared__ float sred[2];
    if ((t & 31) == 0) sred[t >> 5] = ss;
    __syncthreads();
    float tot = sred[0] + sred[1];
    float inv = 1.0f / fmaxf(sqrtf(tot), 1e-12f);
    __half2 h0 = __floats2half2_rn(v.x * inv, v.y * inv);
    __half2 h1 = __floats2half2_rn(v.z * inv, v.w * inv);
    __half2* dst = (__half2*)(g_Z + (size_t)row * D_DIM);
    dst[t * 2]     = h0;
    dst[t * 2 + 1] = h1;
}

// ============ kernel 2: fused Gram-GEMM + exp row-sum (raw, incl. diagonal) ============
// grid (COL_SPLITS, 64), 256 threads = 8 warps as 4(M) x 2(N).
// fp16-accumulate in chunks of K=64 (4 MMAs), drained into fp32.
__global__ void __launch_bounds__(256, 1) k_gemm_denom() {
    extern __shared__ __align__(1024) char smem[];
    const int tid    = threadIdx.x;
    const int wid    = tid >> 5;
    const int lane   = tid & 31;
    const int warp_m = wid & 3;
    const int warp_n = wid >> 2;
    uint32_t sbase = smem_u32(smem);

    const int row_base = blockIdx.y * TILE;
    const int col_base = blockIdx.x * COLS_PER_CTA;

    load_tile(sbase + SMEM_A,  g_Z + (size_t)row_base * D_DIM, tid);
    load_tile(sbase + SMEM_B0, g_Z + (size_t)col_base * D_DIM, tid);
    asm volatile("cp.async.commit_group;" ::: "memory");

    const uint32_t lrow = (uint32_t)(lane & 15) * ROW_BYTES + (uint32_t)(lane >> 4) * 16;
    const uint32_t abase = sbase + SMEM_A + (uint32_t)(warp_m * 32) * ROW_BYTES + lrow;
    const uint32_t boff  = (uint32_t)(warp_n * 64) * ROW_BYTES + lrow;

    float rsum[2][2] = {{0.f, 0.f}, {0.f, 0.f}};   // [m-tile][row-half]

    for (int jt = 0; jt < NTILES; ++jt) {
        if (jt + 1 < NTILES) {
            load_tile(sbase + ((jt + 1) & 1 ? SMEM_B1 : SMEM_B0),
                      g_Z + (size_t)(col_base + (jt + 1) * TILE) * D_DIM, tid);
            asm volatile("cp.async.commit_group;" ::: "memory");
            asm volatile("cp.async.wait_group 1;" ::: "memory");
        } else {
            asm volatile("cp.async.wait_group 0;" ::: "memory");
        }
        __syncthreads();   // B[jt] visible; prefetch buffer was released last iter

        const uint32_t bbase = sbase + ((jt & 1) ? SMEM_B1 : SMEM_B0) + boff;

        float4 acc32[2][8];
#pragma unroll
        for (int mi = 0; mi < 2; ++mi)
#pragma unroll
            for (int nt = 0; nt < 8; ++nt) acc32[mi][nt] = make_float4(0.f, 0.f, 0.f, 0.f);

#pragma unroll
        for (int kc = 0; kc < 4; ++kc) {           // 4 chunks of K=64
            uint32_t acc16[2][8][2];
#pragma unroll
            for (int mi = 0; mi < 2; ++mi)
#pragma unroll
                for (int nt = 0; nt < 8; ++nt) { acc16[mi][nt][0] = 0u; acc16[mi][nt][1] = 0u; }

#pragma unroll
            for (int k4 = 0; k4 < 4; ++k4) {
                const uint32_t koff = (uint32_t)(kc * 4 + k4) * 32;
                uint32_t a0[4], a1[4];
                ldsm_x4(abase + koff, a0);
                ldsm_x4(abase + 16u * ROW_BYTES + koff, a1);
                uint32_t bf[4][4];
#pragma unroll
                for (int bt = 0; bt < 4; ++bt)
                    ldsm_x4(bbase + (uint32_t)(bt * 16) * ROW_BYTES + koff, bf[bt]);
#pragma unroll
                for (int bt = 0; bt < 4; ++bt) {
                    mma16816_f16(acc16[0][2 * bt],     a0, bf[bt][0], bf[bt][2]);
                    mma16816_f16(acc16[0][2 * bt + 1], a0, bf[bt][1], bf[bt][3]);
                    mma16816_f16(acc16[1][2 * bt],     a1, bf[bt][0], bf[bt][2]);
                    mma16816_f16(acc16[1][2 * bt + 1], a1, bf[bt][1], bf[bt][3]);
                }
            }
            // drain chunk into fp32
#pragma unroll
            for (int mi = 0; mi < 2; ++mi)
#pragma unroll
                for (int nt = 0; nt < 8; ++nt) {
                    float2 f0 = __half22float2(*(const __half2*)&acc16[mi][nt][0]);
                    float2 f1 = __half22float2(*(const __half2*)&acc16[mi][nt][1]);
                    acc32[mi][nt].x += f0.x;
                    acc32[mi][nt].y += f0.y;
                    acc32[mi][nt].z += f1.x;
                    acc32[mi][nt].w += f1.y;
                }
        }
        __syncthreads();   // done reading B[jt]; buffer reusable next iter

        // epilogue: exp(2*sim) row-sum, NO diagonal mask (self-term removed in k_loss)
#pragma unroll
        for (int mi = 0; mi < 2; ++mi) {
            float s0 = 0.f, s1 = 0.f;
#pragma unroll
            for (int nt = 0; nt < 8; ++nt) {
                float4 c = acc32[mi][nt];
                s0 += ex2f(c.x * EXP_K) + ex2f(c.y * EXP_K);
                s1 += ex2f(c.z * EXP_K) + ex2f(c.w * EXP_K);
            }
            rsum[mi][0] += s0;
            rsum[mi][1] += s1;
        }
    }

    // reduce across the 4 lanes sharing a row
    float* dsum = (float*)(smem + SMEM_DSUM);
#pragma unroll
    for (int mi = 0; mi < 2; ++mi)
#pragma unroll
        for (int h = 0; h < 2; ++h) {
            float v = rsum[mi][h];
            v += __shfl_xor_sync(0xffffffffu, v, 1);
            v += __shfl_xor_sync(0xffffffffu, v, 2);
            rsum[mi][h] = v;
        }
    if ((lane & 3) == 0 && warp_n == 0) {
#pragma unroll
        for (int mi = 0; mi < 2; ++mi)
#pragma unroll
            for (int h = 0; h < 2; ++h)
                dsum[warp_m * 32 + mi * 16 + h * 8 + (lane >> 2)] = rsum[mi][h];
    }
    __syncthreads();
    if ((lane & 3) == 0 && warp_n == 1) {
#pragma unroll
        for (int mi = 0; mi < 2; ++mi)
#pragma unroll
            for (int h = 0; h < 2; ++h) {
                int rl = warp_m * 32 + mi * 16 + h * 8 + (lane >> 2);
                g_denom[blockIdx.x * N_TOT + row_base + rl] = dsum[rl] + rsum[mi][h];
            }
    }
}

// ============ kernel 3: positives + self-term correction + atomic final sum ============
// Pair i: contribution = -4*pos + log(d_i) + log(d_{i+B}), d_x = raw_x - exp(2*selfdot_x)
__global__ void __launch_bounds__(256) k_loss_partial(float* __restrict__ out) {
    int wid  = threadIdx.x >> 5;
    int lane = threadIdx.x & 31;
    float wacc = 0.0f;
#pragma unroll 1
    for (int qq = 0; qq < 8; ++qq) {
        int i = blockIdx.x * 64 + wid * 8 + qq;   // 0..4095 (grid 64)
        uint4 a = ((const uint4*)(g_Z + (size_t)i * D_DIM))[lane];
        uint4 b = ((const uint4*)(g_Z + (size_t)(i + B_ROWS) * D_DIM))[lane];
        const __half2* pa = (const __half2*)&a;
        const __half2* pb = (const __half2*)&b;
        float d = 0.f, saa = 0.f, sbb = 0.f;
#pragma unroll
        for (int j = 0; j < 4; ++j) {
            float2 fa = __half22float2(pa[j]);
            float2 fb = __half22float2(pb[j]);
            d   += fa.x * fb.x + fa.y * fb.y;
            saa += fa.x * fa.x + fa.y * fa.y;
            sbb += fb.x * fb.x + fb.y * fb.y;
        }
#pragma unroll
        for (int o = 16; o; o >>= 1) {
            d   += __shfl_xor_sync(0xffffffffu, d, o);
            saa += __shfl_xor_sync(0xffffffffu, saa, o);
            sbb += __shfl_xor_sync(0xffffffffu, sbb, o);
        }
        if (lane == 0) {
            float di = g_denom[i] + g_denom[N_TOT + i] - exp2f(saa * EXP_K);
            float dj = g_denom[i + B_ROWS] + g_denom[N_TOT + i + B_ROWS] - exp2f(sbb * EXP_K);
            wacc += -4.0f * d + logf(di) + logf(dj);
        }
    }
    __shared__ float sacc[8];
    if (lane == 0) sacc[wid] = wacc;
    __syncthreads();
    if (threadIdx.x == 0) {
        float s = 0.0f;
#pragma unroll
        for (int w = 0; w < 8; ++w) s += sacc[w];
        atomicAdd(out, s * (1.0f / (float)N_TOT));
    }
}

// ============ launch ============
extern "C" void kernel_launch(void* const* d_in, const int* in_sizes, int n_in,
                              void* d_out, int out_size) {
    const float* q = (const float*)d_in[0];
    const float* p = (const float*)d_in[1];
    (void)in_sizes; (void)n_in; (void)out_size;

    static bool attr_set = false;
    if (!attr_set) {
        cudaFuncSetAttribute(k_gemm_denom, cudaFuncAttributeMaxDynamicSharedMemorySize, SMEM_TOTAL);
        attr_set = true;
    }

    k_normalize<<<N_TOT, 64>>>(q, p, (float*)d_out);
    dim3 grid(COL_SPLITS, N_TOT / TILE);    // (2, 64)
    k_gemm_denom<<<grid, 256, SMEM_TOTAL>>>();
    k_loss_partial<<<64, 256>>>((float*)d_out);
}

// round 4
// speedup vs baseline: 1.7758x; 1.7758x over previous
#include <cuda_runtime.h>
#include <cuda_fp16.h>
#include <cstdint>

#define DINLINE __device__ __forceinline__

static constexpr int B_ROWS = 4096;
static constexpr int D_DIM  = 256;
static constexpr int N_TOT  = 8192;
static constexpr int TILE   = 128;
static constexpr int NRT    = 64;            // 64 row-tiles of 128

static constexpr float EXP_K = 2.8853900817779268f;  // 2/ln(2): exp(2s)=2^(s*K)

// ---- device scratch ----
__device__ __align__(16) __half g_Z[N_TOT * D_DIM];
__device__ float g_denom[N_TOT];             // raw denominators incl. diagonal

// ============ helpers ============
DINLINE uint32_t smem_u32(const void* p) {
    uint32_t a;
    asm("{ .reg .u64 t; cvta.to.shared.u64 t, %1; cvt.u32.u64 %0, t; }" : "=r"(a) : "l"(p));
    return a;
}
DINLINE void ldsm_x4(uint32_t addr, uint32_t r[4]) {
    asm volatile("ldmatrix.sync.aligned.m8n8.x4.shared.b16 {%0,%1,%2,%3}, [%4];"
                 : "=r"(r[0]), "=r"(r[1]), "=r"(r[2]), "=r"(r[3]) : "r"(addr));
}
DINLINE void mma16816(float4& c, const uint32_t a[4], uint32_t b0, uint32_t b1) {
    asm volatile(
        "mma.sync.aligned.m16n8k16.row.col.f32.f16.f16.f32 "
        "{%0,%1,%2,%3}, {%4,%5,%6,%7}, {%8,%9}, {%0,%1,%2,%3};"
        : "+f"(c.x), "+f"(c.y), "+f"(c.z), "+f"(c.w)
        : "r"(a[0]), "r"(a[1]), "r"(a[2]), "r"(a[3]), "r"(b0), "r"(b1));
}
DINLINE float ex2f(float x) {
    float e;
    asm("ex2.approx.f32 %0, %1;" : "=f"(e) : "f"(x));
    return e;
}

// ============ SMEM layout ============
static constexpr int ROW_BYTES  = 528;               // 256 fp16 + 16B pad
static constexpr int TILE_BYTES = 128 * ROW_BYTES;   // 67584
static constexpr int SMEM_DSUM  = 0;                 // 128 floats
static constexpr int SMEM_CPART = 512;               // 4 x 128 floats
static constexpr int SMEM_A     = 4096;
static constexpr int SMEM_B0    = SMEM_A + TILE_BYTES;
static constexpr int SMEM_B1    = SMEM_B0 + TILE_BYTES;
static constexpr int SMEM_TOTAL = SMEM_B1 + TILE_BYTES;   // 206848

DINLINE void load_tile(uint32_t smem_dst, const __half* gsrc, int tid) {
#pragma unroll
    for (int i = 0; i < 16; ++i) {
        int u = tid + i * 256;
        int r = u >> 5, c = u & 31;
        uint32_t saddr = smem_dst + (uint32_t)r * ROW_BYTES + (uint32_t)c * 16;
        const char* g = (const char*)gsrc + (size_t)u * 16;
        asm volatile("cp.async.cg.shared.global [%0], [%1], 16;" :: "r"(saddr), "l"(g));
    }
}

// ============ kernel 1: normalize + zero denom/out ============
__global__ void __launch_bounds__(64) k_normalize(const float* __restrict__ q,
                                                  const float* __restrict__ p,
                                                  float* __restrict__ out) {
    int row = blockIdx.x;
    if (threadIdx.x == 0) {
        g_denom[row] = 0.0f;
        if (row == 0) out[0] = 0.0f;
    }
    const float* src = (row < B_ROWS) ? q + (size_t)row * D_DIM
                                      : p + (size_t)(row - B_ROWS) * D_DIM;
    int t = threadIdx.x;
    float4 v = ((const float4*)src)[t];
    float ss = v.x * v.x + v.y * v.y + v.z * v.z + v.w * v.w;
#pragma unroll
    for (int o = 16; o; o >>= 1) ss += __shfl_xor_sync(0xffffffffu, ss, o);
    __shared__ float sred[2];
    if ((t & 31) == 0) sred[t >> 5] = ss;
    __syncthreads();
    float inv = 1.0f / fmaxf(sqrtf(sred[0] + sred[1]), 1e-12f);
    __half2 h0 = __floats2half2_rn(v.x * inv, v.y * inv);
    __half2 h1 = __floats2half2_rn(v.z * inv, v.w * inv);
    __half2* dst = (__half2*)(g_Z + (size_t)row * D_DIM);
    dst[t * 2]     = h0;
    dst[t * 2 + 1] = h1;
}

// ============ kernel 2: upper-triangle Gram + exp sums (rows & cols) ============
// 128 CTAs: (p, c4) = (bid>>2, bid&3). Strips it = p and 63-p; jt = it+c4, +4...
__global__ void __launch_bounds__(256, 1) k_gemm_denom() {
    extern __shared__ __align__(1024) char smem[];
    const int tid    = threadIdx.x;
    const int wid    = tid >> 5;
    const int lane   = tid & 31;
    const int warp_m = wid & 3;
    const int warp_n = wid >> 2;
    uint32_t sbase = smem_u32(smem);
    float* dsum = (float*)(smem + SMEM_DSUM);
    float* cpart = (float*)(smem + SMEM_CPART);    // [4][128]

    const int p  = blockIdx.x >> 2;
    const int c4 = blockIdx.x & 3;

    const uint32_t lrow = (uint32_t)(lane & 15) * ROW_BYTES + (uint32_t)(lane >> 4) * 16;
    const uint32_t abase = sbase + SMEM_A + (uint32_t)(warp_m * 32) * ROW_BYTES + lrow;
    const uint32_t boff  = (uint32_t)(warp_n * 64) * ROW_BYTES + lrow;

#pragma unroll 1
    for (int s = 0; s < 2; ++s) {
        const int it = s ? (63 - p) : p;
        const int first = it + c4;
        if (first >= NRT) continue;                      // uniform per CTA
        const int njt = ((NRT - 1 - first) >> 2) + 1;

        load_tile(sbase + SMEM_A,  g_Z + (size_t)it * TILE * D_DIM, tid);
        load_tile(sbase + SMEM_B0, g_Z + (size_t)first * TILE * D_DIM, tid);
        asm volatile("cp.async.commit_group;" ::: "memory");

        float rsum[2][2] = {{0.f, 0.f}, {0.f, 0.f}};

#pragma unroll 1
        for (int idx = 0; idx < njt; ++idx) {
            const int jt = first + idx * 4;
            if (idx + 1 < njt) {
                load_tile(sbase + ((idx + 1) & 1 ? SMEM_B1 : SMEM_B0),
                          g_Z + (size_t)(jt + 4) * TILE * D_DIM, tid);
                asm volatile("cp.async.commit_group;" ::: "memory");
                asm volatile("cp.async.wait_group 1;" ::: "memory");
            } else {
                asm volatile("cp.async.wait_group 0;" ::: "memory");
            }
            __syncthreads();

            const uint32_t bbase = sbase + ((idx & 1) ? SMEM_B1 : SMEM_B0) + boff;

            float4 acc[2][8];
#pragma unroll
            for (int mi = 0; mi < 2; ++mi)
#pragma unroll
                for (int nt = 0; nt < 8; ++nt) acc[mi][nt] = make_float4(0.f, 0.f, 0.f, 0.f);

#pragma unroll
            for (int ks = 0; ks < 16; ++ks) {
                uint32_t a0[4], a1[4];
                ldsm_x4(abase + (uint32_t)ks * 32, a0);
                ldsm_x4(abase + 16u * ROW_BYTES + (uint32_t)ks * 32, a1);
                uint32_t bf[4][4];
#pragma unroll
                for (int bt = 0; bt < 4; ++bt)
                    ldsm_x4(bbase + (uint32_t)(bt * 16) * ROW_BYTES + (uint32_t)ks * 32, bf[bt]);
#pragma unroll
                for (int bt = 0; bt < 4; ++bt) {
                    mma16816(acc[0][2 * bt],     a0, bf[bt][0], bf[bt][2]);
                    mma16816(acc[0][2 * bt + 1], a0, bf[bt][1], bf[bt][3]);
                    mma16816(acc[1][2 * bt],     a1, bf[bt][0], bf[bt][2]);
                    mma16816(acc[1][2 * bt + 1], a1, bf[bt][1], bf[bt][3]);
                }
            }
            __syncthreads();    // B[idx] reads done; buffer reusable next iter

            // epilogue: exps feed row sums always, col sums if off-diagonal
            const bool offdiag = (jt != it);
            float colacc[16];
#pragma unroll
            for (int i = 0; i < 16; ++i) colacc[i] = 0.f;
#pragma unroll
            for (int mi = 0; mi < 2; ++mi) {
                float s0 = 0.f, s1 = 0.f;
#pragma unroll
                for (int nt = 0; nt < 8; ++nt) {
                    float4 c = acc[mi][nt];
                    float ex = ex2f(c.x * EXP_K), ey = ex2f(c.y * EXP_K);
                    float ez = ex2f(c.z * EXP_K), ew = ex2f(c.w * EXP_K);
                    s0 += ex + ey;
                    s1 += ez + ew;
                    colacc[nt * 2]     += ex + ez;
                    colacc[nt * 2 + 1] += ey + ew;
                }
                rsum[mi][0] += s0;
                rsum[mi][1] += s1;
            }
            if (offdiag) {
#pragma unroll
                for (int i = 0; i < 16; ++i) {
                    float v = colacc[i];
                    v += __shfl_xor_sync(0xffffffffu, v, 4);
                    v += __shfl_xor_sync(0xffffffffu, v, 8);
                    v += __shfl_xor_sync(0xffffffffu, v, 16);
                    colacc[i] = v;
                }
                if (lane < 4) {
#pragma unroll
                    for (int nt = 0; nt < 8; ++nt) {
                        cpart[warp_m * 128 + warp_n * 64 + nt * 8 + 2 * lane]     = colacc[nt * 2];
                        cpart[warp_m * 128 + warp_n * 64 + nt * 8 + 2 * lane + 1] = colacc[nt * 2 + 1];
                    }
                }
                __syncthreads();
                if (tid < 128) {
                    float v = cpart[tid] + cpart[128 + tid] + cpart[256 + tid] + cpart[384 + tid];
                    atomicAdd(&g_denom[jt * TILE + tid], v);
                }
            }
        }

        // strip row-sum write
#pragma unroll
        for (int mi = 0; mi < 2; ++mi)
#pragma unroll
            for (int h = 0; h < 2; ++h) {
                float v = rsum[mi][h];
                v += __shfl_xor_sync(0xffffffffu, v, 1);
                v += __shfl_xor_sync(0xffffffffu, v, 2);
                rsum[mi][h] = v;
            }
        __syncthreads();
        if ((lane & 3) == 0 && warp_n == 0) {
#pragma unroll
            for (int mi = 0; mi < 2; ++mi)
#pragma unroll
                for (int h = 0; h < 2; ++h)
                    dsum[warp_m * 32 + mi * 16 + h * 8 + (lane >> 2)] = rsum[mi][h];
        }
        __syncthreads();
        if ((lane & 3) == 0 && warp_n == 1) {
#pragma unroll
            for (int mi = 0; mi < 2; ++mi)
#pragma unroll
                for (int h = 0; h < 2; ++h) {
                    int rl = warp_m * 32 + mi * 16 + h * 8 + (lane >> 2);
                    atomicAdd(&g_denom[it * TILE + rl], dsum[rl] + rsum[mi][h]);
                }
        }
        __syncthreads();
    }
}

// ============ kernel 3: positives + self-term + final sum ============
__global__ void __launch_bounds__(256) k_loss_partial(float* __restrict__ out) {
    int wid  = threadIdx.x >> 5;
    int lane = threadIdx.x & 31;
    float wacc = 0.0f;
#pragma unroll 1
    for (int qq = 0; qq < 8; ++qq) {
        int i = blockIdx.x * 64 + wid * 8 + qq;
        uint4 a = ((const uint4*)(g_Z + (size_t)i * D_DIM))[lane];
        uint4 b = ((const uint4*)(g_Z + (size_t)(i + B_ROWS) * D_DIM))[lane];
        const __half2* pa = (const __half2*)&a;
        const __half2* pb = (const __half2*)&b;
        float d = 0.f, saa = 0.f, sbb = 0.f;
#pragma unroll
        for (int j = 0; j < 4; ++j) {
            float2 fa = __half22float2(pa[j]);
            float2 fb = __half22float2(pb[j]);
            d   += fa.x * fb.x + fa.y * fb.y;
            saa += fa.x * fa.x + fa.y * fa.y;
            sbb += fb.x * fb.x + fb.y * fb.y;
        }
#pragma unroll
        for (int o = 16; o; o >>= 1) {
            d   += __shfl_xor_sync(0xffffffffu, d, o);
            saa += __shfl_xor_sync(0xffffffffu, saa, o);
            sbb += __shfl_xor_sync(0xffffffffu, sbb, o);
        }
        if (lane == 0) {
            float di = g_denom[i] - exp2f(saa * EXP_K);
            float dj = g_denom[i + B_ROWS] - exp2f(sbb * EXP_K);
            wacc += -4.0f * d + logf(di) + logf(dj);
        }
    }
    __shared__ float sacc[8];
    if (lane == 0) sacc[wid] = wacc;
    __syncthreads();
    if (threadIdx.x == 0) {
        float s = 0.0f;
#pragma unroll
        for (int w = 0; w < 8; ++w) s += sacc[w];
        atomicAdd(out, s * (1.0f / (float)N_TOT));
    }
}

// ============ launch ============
extern "C" void kernel_launch(void* const* d_in, const int* in_sizes, int n_in,
                              void* d_out, int out_size) {
    const float* q = (const float*)d_in[0];
    const float* p = (const float*)d_in[1];
    (void)in_sizes; (void)n_in; (void)out_size;

    static bool attr_set = false;
    if (!attr_set) {
        cudaFuncSetAttribute(k_gemm_denom, cudaFuncAttributeMaxDynamicSharedMemorySize, SMEM_TOTAL);
        attr_set = true;
    }

    k_normalize<<<N_TOT, 64>>>(q, p, (float*)d_out);
    k_gemm_denom<<<128, 256, SMEM_TOTAL>>>();
    k_loss_partial<<<64, 256>>>((float*)d_out);
}